// round 11
// baseline (speedup 1.0000x reference)
#include <cuda_runtime.h>
#include <cuda_fp16.h>
#include <math.h>
#include <stdint.h>

#define B_  2
#define S_  2048
#define D_  256
#define H_  8
#define C_  32
#define OUT_ 256
#define WIN_ 32
#define M_  (B_ * S_)
#define GRID_ 148

// -------- device scratch --------
__device__ __align__(16) __half g_X [3 * M_ * D_];
__device__ __align__(16) __half g_Wh[5 * 256 * 256];
__device__ __align__(16) __half g_Wl[5 * 256 * 256];
__device__ __align__(16) __half g_Qh[M_ * D_], g_Ql[M_ * D_];
__device__ __align__(16) __half g_K [M_ * D_];
__device__ __align__(16) __half g_V [M_ * D_];
__device__ __align__(16) float  g_G [M_ * D_];
__device__ __align__(16) __half g_O [M_ * D_];

__device__ unsigned g_sync_cnt;   // zero-init; reset at end of each launch
__device__ unsigned g_exit_cnt;

// ================= helpers =================
__device__ __forceinline__ uint32_t smem_u32(const void* p) {
    uint32_t a;
    asm("{ .reg .u64 t; cvta.to.shared.u64 t, %1; cvt.u32.u64 %0, t; }" : "=r"(a) : "l"(p));
    return a;
}
#define LDM_X4(r, addr) \
    asm volatile("ldmatrix.sync.aligned.m8n8.x4.shared.b16 {%0,%1,%2,%3}, [%4];" \
        : "=r"((r)[0]), "=r"((r)[1]), "=r"((r)[2]), "=r"((r)[3]) : "r"(addr))
#define LDM_X2(r, addr) \
    asm volatile("ldmatrix.sync.aligned.m8n8.x2.shared.b16 {%0,%1}, [%2];" \
        : "=r"((r)[0]), "=r"((r)[1]) : "r"(addr))
#define LDM_X2_T(r, addr) \
    asm volatile("ldmatrix.sync.aligned.m8n8.x2.trans.shared.b16 {%0,%1}, [%2];" \
        : "=r"((r)[0]), "=r"((r)[1]) : "r"(addr))
#define MMA_F16(c, a, b) \
    asm volatile("mma.sync.aligned.m16n8k16.row.col.f32.f16.f16.f32 " \
        "{%0,%1,%2,%3}, {%4,%5,%6,%7}, {%8,%9}, {%0,%1,%2,%3};" \
        : "+f"((c)[0]), "+f"((c)[1]), "+f"((c)[2]), "+f"((c)[3]) \
        : "r"((a)[0]), "r"((a)[1]), "r"((a)[2]), "r"((a)[3]), "r"((b)[0]), "r"((b)[1]))
#define CP_ASYNC16(dst, src) \
    asm volatile("cp.async.cg.shared.global [%0], [%1], 16;" :: "r"(dst), "l"(src))
#define CP_ASYNC16_P(dst, src, sz) \
    asm volatile("cp.async.cg.shared.global [%0], [%1], 16, %2;" :: "r"(dst), "l"(src), "r"(sz))
#define CP_COMMIT() asm volatile("cp.async.commit_group;" ::: "memory")
#define CP_WAIT(n)  asm volatile("cp.async.wait_group %0;" :: "n"(n) : "memory")

__device__ __forceinline__ void split2h(float a, float b, uint32_t& h, uint32_t& l) {
    __half2 hi2 = __floats2half2_rn(a, b);
    float ra = a - __low2float(hi2);
    float rb = b - __high2float(hi2);
    __half2 lo2 = __floats2half2_rn(ra, rb);
    h = *reinterpret_cast<uint32_t*>(&hi2);
    l = *reinterpret_cast<uint32_t*>(&lo2);
}

__device__ __forceinline__ void grid_barrier(unsigned target) {
    __syncthreads();
    if (threadIdx.x == 0) {
        __threadfence();
        atomicAdd(&g_sync_cnt, 1u);
        while (*(volatile unsigned*)&g_sync_cnt < target) __nanosleep(64);
        __threadfence();
    }
    __syncthreads();
}

// ================= GEMM tile: BM=128, BN=64, BK=128 (2 chunks, both prefetched) =================
#define G_ROW   272
#define G_CHUNK (256 * G_ROW)              // 69632
#define SMEM_MEGA (2 * G_CHUNK)            // 139264

// MODE: 0 = split half out (Q), 1 = f32+bias+sigmoid (G), 2 = f32+bias (final out), 3 = single half out
template <int MODE>
__device__ __forceinline__ void gemm_tile(const __half* __restrict__ A,
                                          const __half* __restrict__ Bh, const __half* __restrict__ Bl,
                                          const float* __restrict__ bias,
                                          float* __restrict__ Yf,
                                          __half* __restrict__ Yh, __half* __restrict__ Yl,
                                          int m0, int n0, uint32_t sb) {
    const int tid = threadIdx.x, wid = tid >> 5, lane = tid & 31;
    const int warp_m = wid & 3, warp_n = wid >> 2;      // 4 x 2 warps, warp tile 32x32
    const int lm_row = lane & 15, lm_chunk = (lane >> 4) * 16;

    __syncthreads();   // previous tile's smem reads complete

    // prefetch both K-chunks (rows: 0-127 A, 128-191 Bh, 192-255 Bl; 256B/row)
#pragma unroll 1
    for (int kc = 0; kc < 2; kc++) {
        for (int task = tid; task < 4096; task += 256) {
            int row = task >> 4, ch = task & 15;
            const __half* s;
            if (row < 128)      s = A  + (size_t)(m0 + row) * 256 + kc * 128 + ch * 8;
            else if (row < 192) s = Bh + (size_t)(n0 + row - 128) * 256 + kc * 128 + ch * 8;
            else                s = Bl + (size_t)(n0 + row - 192) * 256 + kc * 128 + ch * 8;
            CP_ASYNC16(sb + kc * G_CHUNK + row * G_ROW + ch * 16, s);
        }
        CP_COMMIT();
    }

    float acc[2][4][4];
#pragma unroll
    for (int i = 0; i < 2; i++)
#pragma unroll
        for (int j = 0; j < 4; j++)
#pragma unroll
            for (int q = 0; q < 4; q++) acc[i][j][q] = 0.f;

#pragma unroll
    for (int kc = 0; kc < 2; kc++) {
        if (kc == 0) CP_WAIT(1); else CP_WAIT(0);
        __syncthreads();
        const uint32_t bb = sb + kc * G_CHUNK;
#pragma unroll
        for (int ks = 0; ks < 8; ks++) {
            const uint32_t kbyte = ks * 32 + lm_chunk;
            uint32_t a[2][4], bh[4][2], bl[4][2];
#pragma unroll
            for (int mf = 0; mf < 2; mf++) {
                uint32_t off = (uint32_t)((warp_m * 32 + mf * 16 + lm_row) * G_ROW) + kbyte;
                LDM_X4(a[mf], bb + off);
            }
#pragma unroll
            for (int np = 0; np < 2; np++) {
                uint32_t offh = (uint32_t)((128 + warp_n * 32 + np * 16 + lm_row) * G_ROW) + kbyte;
                uint32_t offl = (uint32_t)((192 + warp_n * 32 + np * 16 + lm_row) * G_ROW) + kbyte;
                uint32_t th[4], tl[4];
                LDM_X4(th, bb + offh);
                LDM_X4(tl, bb + offl);
                bh[np * 2][0] = th[0]; bh[np * 2][1] = th[2];
                bh[np * 2 + 1][0] = th[1]; bh[np * 2 + 1][1] = th[3];
                bl[np * 2][0] = tl[0]; bl[np * 2][1] = tl[2];
                bl[np * 2 + 1][0] = tl[1]; bl[np * 2 + 1][1] = tl[3];
            }
#pragma unroll
            for (int mf = 0; mf < 2; mf++)
#pragma unroll
                for (int nf = 0; nf < 4; nf++) {
                    MMA_F16(acc[mf][nf], a[mf], bh[nf]);
                    MMA_F16(acc[mf][nf], a[mf], bl[nf]);
                }
        }
    }

    // epilogue
#pragma unroll
    for (int mf = 0; mf < 2; mf++) {
        int row = m0 + warp_m * 32 + mf * 16 + (lane >> 2);
#pragma unroll
        for (int nf = 0; nf < 4; nf++) {
            int col = n0 + warp_n * 32 + nf * 8 + (lane & 3) * 2;
            float v0 = acc[mf][nf][0], v1 = acc[mf][nf][1];
            float v2 = acc[mf][nf][2], v3 = acc[mf][nf][3];
            if (MODE == 1 || MODE == 2) {
                float b0 = bias[col], b1 = bias[col + 1];
                v0 += b0; v1 += b1; v2 += b0; v3 += b1;
                if (MODE == 1) {
                    v0 = 1.f / (1.f + __expf(-v0));
                    v1 = 1.f / (1.f + __expf(-v1));
                    v2 = 1.f / (1.f + __expf(-v2));
                    v3 = 1.f / (1.f + __expf(-v3));
                }
                *reinterpret_cast<float2*>(Yf + (size_t)row * 256 + col)       = make_float2(v0, v1);
                *reinterpret_cast<float2*>(Yf + (size_t)(row + 8) * 256 + col) = make_float2(v2, v3);
            } else if (MODE == 0) {
                uint32_t h0, l0, h1, l1;
                split2h(v0, v1, h0, l0);
                split2h(v2, v3, h1, l1);
                *reinterpret_cast<uint32_t*>(Yh + (size_t)row * 256 + col)       = h0;
                *reinterpret_cast<uint32_t*>(Yl + (size_t)row * 256 + col)       = l0;
                *reinterpret_cast<uint32_t*>(Yh + (size_t)(row + 8) * 256 + col) = h1;
                *reinterpret_cast<uint32_t*>(Yl + (size_t)(row + 8) * 256 + col) = l1;
            } else {
                __half2 a2 = __floats2half2_rn(v0, v1);
                __half2 b2 = __floats2half2_rn(v2, v3);
                *reinterpret_cast<uint32_t*>(Yh + (size_t)row * 256 + col)       = *reinterpret_cast<uint32_t*>(&a2);
                *reinterpret_cast<uint32_t*>(Yh + (size_t)(row + 8) * 256 + col) = *reinterpret_cast<uint32_t*>(&b2);
            }
        }
    }
}

// ================= attention tile (per-tile smem buf) =================
#define A_QH 0
#define A_QL 2560
#define A_K  5120
#define A_V  12800
#define A_PH 20480
#define A_PL 27136
#define A_RED 33792
#define A_BUF 34816
#define QK_ROW 80
#define VT_ROW 208

__device__ __forceinline__ void attn_stage(int idx, int buf, uint32_t sb) {
    const int b = idx >> 9, h = (idx >> 6) & 7, s0 = (idx & 63) << 5;
    const uint32_t ab = sb + buf * A_BUF;
    const int tid = threadIdx.x;
    for (int i = tid; i < 1024; i += 256) {
        uint32_t dst; const __half* src; int ok;
        if (i < 384) {
            int row = i >> 2, ch = i & 3;
            int t = s0 - 32 + row;
            ok = (t >= 0 && t < S_);
            int tc = ok ? t : 0;
            src = g_K + ((size_t)(b * S_ + tc) * 256 + h * 32 + ch * 8);
            dst = ab + A_K + row * QK_ROW + ch * 16;
        } else if (i < 768) {
            int j = i - 384;
            int row = j >> 2, ch = j & 3;
            int t = s0 - 32 + row;
            ok = (t >= 0 && t < S_);
            int tc = ok ? t : 0;
            src = g_V + ((size_t)(b * S_ + tc) * 256 + h * 32 + ch * 8);
            dst = ab + A_V + row * QK_ROW + ch * 16;
        } else if (i < 896) {
            int j = i - 768;
            int row = j >> 2, ch = j & 3;
            ok = 1;
            src = g_Qh + ((size_t)(b * S_ + s0 + row) * 256 + h * 32 + ch * 8);
            dst = ab + A_QH + row * QK_ROW + ch * 16;
        } else {
            int j = i - 896;
            int row = j >> 2, ch = j & 3;
            ok = 1;
            src = g_Ql + ((size_t)(b * S_ + s0 + row) * 256 + h * 32 + ch * 8);
            dst = ab + A_QL + row * QK_ROW + ch * 16;
        }
        CP_ASYNC16_P(dst, src, ok ? 16 : 0);
    }
}

__device__ __forceinline__ void attn_compute(int idx, int buf, uint32_t sb, char* smem) {
    const int b = idx >> 9, h = (idx >> 6) & 7, s0 = (idx & 63) << 5;
    const uint32_t ab = sb + buf * A_BUF;
    char* ap = smem + buf * A_BUF;
    float* red = reinterpret_cast<float*>(ap + A_RED);
    const int tid = threadIdx.x, wid = tid >> 5, lane = tid & 31;
    const int lm_row = lane & 15, lm_chunk = (lane >> 4) * 16;

    const int mf = wid >> 2;
    const int nfb = (wid & 3) * 3;
    float scH[3][4], scL[3][4];
#pragma unroll
    for (int j = 0; j < 3; j++)
#pragma unroll
        for (int q = 0; q < 4; q++) { scH[j][q] = 0.f; scL[j][q] = 0.f; }

#pragma unroll
    for (int kf = 0; kf < 2; kf++) {
        uint32_t qh[4], ql[4];
        uint32_t aoff = (uint32_t)((mf * 16 + lm_row) * QK_ROW) + kf * 32 + lm_chunk;
        LDM_X4(qh, ab + A_QH + aoff);
        LDM_X4(ql, ab + A_QL + aoff);
#pragma unroll
        for (int j = 0; j < 3; j++) {
            uint32_t kk[2];
            uint32_t boff = (uint32_t)(((nfb + j) * 8 + (lane & 7)) * QK_ROW) + kf * 32 +
                            (((lane >> 3) & 1) * 16);
            LDM_X2(kk, ab + A_K + boff);
            MMA_F16(scH[j], qh, kk);
            MMA_F16(scL[j], ql, kk);
        }
    }

    const float rsC = 0.17677669529663689f;
    const int r0 = mf * 16 + (lane >> 2);
    const int r1 = r0 + 8;
    float sv[3][4];
#pragma unroll
    for (int j = 0; j < 3; j++) {
        int nb = (nfb + j) * 8 + (lane & 3) * 2;
#pragma unroll
        for (int q = 0; q < 4; q++) {
            int n = nb + (q & 1);
            int row = (q < 2) ? r0 : r1;
            int t = s0 - 32 + n;
            bool ok = (n >= row) && (n <= row + 64) && (t >= 0) && (t < S_);
            sv[j][q] = ok ? (scH[j][q] + scL[j][q]) * rsC : -1e30f;
        }
    }
    float m0v = -1e30f, m1v = -1e30f;
#pragma unroll
    for (int j = 0; j < 3; j++) {
        m0v = fmaxf(m0v, fmaxf(sv[j][0], sv[j][1]));
        m1v = fmaxf(m1v, fmaxf(sv[j][2], sv[j][3]));
    }
    m0v = fmaxf(m0v, __shfl_xor_sync(0xffffffffu, m0v, 1));
    m0v = fmaxf(m0v, __shfl_xor_sync(0xffffffffu, m0v, 2));
    m1v = fmaxf(m1v, __shfl_xor_sync(0xffffffffu, m1v, 1));
    m1v = fmaxf(m1v, __shfl_xor_sync(0xffffffffu, m1v, 2));
    if ((lane & 3) == 0) {
        red[r0 * 8 + (wid & 3)] = m0v;
        red[r1 * 8 + (wid & 3)] = m1v;
    }
    __syncthreads();
    float mx0 = fmaxf(fmaxf(red[r0 * 8 + 0], red[r0 * 8 + 1]),
                      fmaxf(red[r0 * 8 + 2], red[r0 * 8 + 3]));
    float mx1 = fmaxf(fmaxf(red[r1 * 8 + 0], red[r1 * 8 + 1]),
                      fmaxf(red[r1 * 8 + 2], red[r1 * 8 + 3]));
    float e[3][4], sum0 = 0.f, sum1 = 0.f;
#pragma unroll
    for (int j = 0; j < 3; j++) {
        e[j][0] = __expf(sv[j][0] - mx0);
        e[j][1] = __expf(sv[j][1] - mx0);
        e[j][2] = __expf(sv[j][2] - mx1);
        e[j][3] = __expf(sv[j][3] - mx1);
        sum0 += e[j][0] + e[j][1];
        sum1 += e[j][2] + e[j][3];
    }
    sum0 += __shfl_xor_sync(0xffffffffu, sum0, 1);
    sum0 += __shfl_xor_sync(0xffffffffu, sum0, 2);
    sum1 += __shfl_xor_sync(0xffffffffu, sum1, 1);
    sum1 += __shfl_xor_sync(0xffffffffu, sum1, 2);
    if ((lane & 3) == 0) {
        red[r0 * 8 + 4 + (wid & 3)] = sum0;
        red[r1 * 8 + 4 + (wid & 3)] = sum1;
    }
    __syncthreads();
    float inv0 = 1.f / (red[r0 * 8 + 4] + red[r0 * 8 + 5] + red[r0 * 8 + 6] + red[r0 * 8 + 7]);
    float inv1 = 1.f / (red[r1 * 8 + 4] + red[r1 * 8 + 5] + red[r1 * 8 + 6] + red[r1 * 8 + 7]);

#pragma unroll
    for (int j = 0; j < 3; j++) {
        int nb = (nfb + j) * 8 + (lane & 3) * 2;
        uint32_t h0, l0, h1, l1;
        split2h(e[j][0] * inv0, e[j][1] * inv0, h0, l0);
        split2h(e[j][2] * inv1, e[j][3] * inv1, h1, l1);
        *reinterpret_cast<uint32_t*>(ap + A_PH + r0 * VT_ROW + nb * 2) = h0;
        *reinterpret_cast<uint32_t*>(ap + A_PL + r0 * VT_ROW + nb * 2) = l0;
        *reinterpret_cast<uint32_t*>(ap + A_PH + r1 * VT_ROW + nb * 2) = h1;
        *reinterpret_cast<uint32_t*>(ap + A_PL + r1 * VT_ROW + nb * 2) = l1;
    }
    __syncthreads();

    const int nc = wid & 3;
    float oaccH[4] = {0.f, 0.f, 0.f, 0.f};
    float oaccL[4] = {0.f, 0.f, 0.f, 0.f};
#pragma unroll
    for (int kf = 0; kf < 6; kf++) {
        uint32_t ph[4], pl[4], vv[2];
        uint32_t poff = (uint32_t)((mf * 16 + lm_row) * VT_ROW) + kf * 32 + lm_chunk;
        LDM_X4(ph, ab + A_PH + poff);
        LDM_X4(pl, ab + A_PL + poff);
        uint32_t voff = (uint32_t)((kf * 16 + (lane & 15)) * QK_ROW) + nc * 16;
        LDM_X2_T(vv, ab + A_V + voff);
        MMA_F16(oaccH, ph, vv);
        MMA_F16(oaccL, pl, vv);
    }

    {
        int gcol = h * 32 + nc * 8 + (lane & 3) * 2;
        size_t e0 = (size_t)(b * S_ + s0 + r0) * 256 + gcol;
        size_t e1 = (size_t)(b * S_ + s0 + r1) * 256 + gcol;
        float2 gA = *reinterpret_cast<const float2*>(g_G + e0);
        float2 gB = *reinterpret_cast<const float2*>(g_G + e1);
        __half2 o0 = __floats2half2_rn((oaccH[0] + oaccL[0]) * gA.x, (oaccH[1] + oaccL[1]) * gA.y);
        __half2 o1 = __floats2half2_rn((oaccH[2] + oaccL[2]) * gB.x, (oaccH[3] + oaccL[3]) * gB.y);
        *reinterpret_cast<uint32_t*>(g_O + e0) = *reinterpret_cast<uint32_t*>(&o0);
        *reinterpret_cast<uint32_t*>(g_O + e1) = *reinterpret_cast<uint32_t*>(&o1);
    }
}

// ================= the megakernel =================
__global__ void __launch_bounds__(256, 1)
mega_kernel(const float* __restrict__ Qin, const float* __restrict__ Kin,
            const float* __restrict__ Vin, const float* __restrict__ QT,
            const float* __restrict__ KT,  const float* __restrict__ VT,
            const float* __restrict__ GW,  const float* __restrict__ OW,
            const float* __restrict__ Gb,  const float* __restrict__ Ob,
            float* __restrict__ out) {
    extern __shared__ char smem[];
    const uint32_t sb = smem_u32(smem);
    const int bid = blockIdx.x;
    const int tid = threadIdx.x;

    // ---------- phase 0: prep ----------
    for (int blk = bid; blk < 3392; blk += GRID_) {
        if (blk < 3072) {
            int z = blk >> 10;
            int bx = blk & 1023;
            const float* src = (z == 0) ? Qin : (z == 1) ? Kin : Vin;
            size_t base = (size_t)z * (M_ * D_);
            int i = bx * 256 + tid;
            float4 v = reinterpret_cast<const float4*>(src)[i];
            __half2 a = __floats2half2_rn(v.x, v.y);
            __half2 b = __floats2half2_rn(v.z, v.w);
            reinterpret_cast<uint2*>(g_X + base)[i] =
                make_uint2(*reinterpret_cast<uint32_t*>(&a), *reinterpret_cast<uint32_t*>(&b));
        } else if (blk < 3200) {
            int t = blk - 3072;
            int z = t >> 6;
            int bx = t & 63;
            const float* src = (z == 0) ? GW : OW;
            size_t base = (size_t)(3 + z) * 65536;
            int i = bx * 256 + tid;
            float4 v = reinterpret_cast<const float4*>(src)[i];
            uint32_t h0, l0, h1, l1;
            split2h(v.x, v.y, h0, l0);
            split2h(v.z, v.w, h1, l1);
            reinterpret_cast<uint2*>(g_Wh + base)[i] = make_uint2(h0, h1);
            reinterpret_cast<uint2*>(g_Wl + base)[i] = make_uint2(l0, l1);
        } else {
            int t = blk - 3200;
            int z = t >> 6;
            int ky = (t >> 3) & 7;
            int nx = t & 7;
            const float* src = (z == 0) ? QT : (z == 1) ? KT : VT;
            size_t base = (size_t)z * 65536;
            float* tr = reinterpret_cast<float*>(smem);   // 32x33
            int tx = tid & 31, ty = tid >> 5;
            int k0 = ky * 32, n0 = nx * 32;
            __syncthreads();
#pragma unroll
            for (int r = 0; r < 4; r++)
                tr[(ty + r * 8) * 33 + tx] = src[(size_t)(k0 + ty + r * 8) * 256 + n0 + tx];
            __syncthreads();
#pragma unroll
            for (int r = 0; r < 4; r++) {
                int n = n0 + ty + r * 8, k = k0 + tx;
                float v = tr[tx * 33 + ty + r * 8];
                __half h = __float2half(v);
                g_Wh[base + (size_t)n * 256 + k] = h;
                g_Wl[base + (size_t)n * 256 + k] = __float2half(v - __half2float(h));
            }
        }
    }
    grid_barrier(GRID_);

    // ---------- phase 1: projections (512 tiles: z 4 x m 32 x n 4) ----------
    for (int idx = bid; idx < 512; idx += GRID_) {
        int z = idx >> 7, r = idx & 127;
        int m0 = (r >> 2) << 7, n0 = (r & 3) << 6;
        int xslot = (z == 3) ? 2 : z;
        const __half* A  = g_X + (size_t)xslot * (M_ * D_);
        const __half* Bh = g_Wh + (size_t)z * 65536;
        const __half* Bl = g_Wl + (size_t)z * 65536;
        if (z == 0)      gemm_tile<0>(A, Bh, Bl, nullptr, nullptr, g_Qh, g_Ql, m0, n0, sb);
        else if (z == 1) gemm_tile<3>(A, Bh, Bl, nullptr, nullptr, g_K, nullptr, m0, n0, sb);
        else if (z == 2) gemm_tile<3>(A, Bh, Bl, nullptr, nullptr, g_V, nullptr, m0, n0, sb);
        else             gemm_tile<1>(A, Bh, Bl, Gb, g_G, nullptr, nullptr, m0, n0, sb);
    }
    grid_barrier(2 * GRID_);

    // ---------- phase 2: attention (1024 tiles), cross-tile prefetch ----------
    {
        attn_stage(bid, 0, sb);
        CP_COMMIT();
        int buf = 0;
        for (int idx = bid; idx < 1024; idx += GRID_) {
            int nxt = idx + GRID_;
            if (nxt < 1024) { attn_stage(nxt, buf ^ 1, sb); CP_COMMIT(); CP_WAIT(1); }
            else            { CP_WAIT(0); }
            __syncthreads();
            attn_compute(idx, buf, sb, smem);
            __syncthreads();
            buf ^= 1;
        }
    }
    grid_barrier(3 * GRID_);

    // ---------- phase 3: output projection (128 tiles: m 32 x n 4) ----------
    for (int idx = bid; idx < 128; idx += GRID_) {
        int m0 = (idx >> 2) << 7, n0 = (idx & 3) << 6;
        gemm_tile<2>(g_O, g_Wh + 4 * 65536, g_Wl + 4 * 65536, Ob, out, nullptr, nullptr, m0, n0, sb);
    }

    // ---------- exit protocol: reset barrier counters for next replay ----------
    __syncthreads();
    if (tid == 0) {
        __threadfence();
        atomicAdd(&g_exit_cnt, 1u);
        if (bid == 0) {
            while (*(volatile unsigned*)&g_exit_cnt < GRID_) __nanosleep(64);
            g_sync_cnt = 0u;
            g_exit_cnt = 0u;
            __threadfence();
        }
    }
}

// ============================================================
extern "C" void kernel_launch(void* const* d_in, const int* in_sizes, int n_in,
                              void* d_out, int out_size) {
    const float* Qin = (const float*)d_in[0];
    const float* Kin = (const float*)d_in[1];
    const float* Vin = (const float*)d_in[2];
    const float* QT  = (const float*)d_in[3];
    const float* KT  = (const float*)d_in[4];
    const float* VT  = (const float*)d_in[5];
    const float* GW  = (const float*)d_in[6];
    const float* Gb  = (const float*)d_in[7];
    const float* OW  = (const float*)d_in[8];
    const float* Ob  = (const float*)d_in[9];
    float* out = (float*)d_out;

    cudaFuncSetAttribute(mega_kernel, cudaFuncAttributeMaxDynamicSharedMemorySize, SMEM_MEGA);
    mega_kernel<<<GRID_, 256, SMEM_MEGA>>>(Qin, Kin, Vin, QT, KT, VT, GW, OW, Gb, Ob, out);
}

// round 12
// speedup vs baseline: 1.2670x; 1.2670x over previous
#include <cuda_runtime.h>
#include <cuda_fp16.h>
#include <math.h>
#include <stdint.h>

#define B_  2
#define S_  2048
#define D_  256
#define H_  8
#define C_  32
#define OUT_ 256
#define WIN_ 32
#define M_  (B_ * S_)

// -------- device scratch --------
__device__ __align__(16) __half g_X [3 * M_ * D_];
__device__ __align__(16) __half g_Wh[5 * 256 * 256];
__device__ __align__(16) __half g_Wl[5 * 256 * 256];
__device__ __align__(16) __half g_Qh[M_ * D_], g_Ql[M_ * D_];
__device__ __align__(16) __half g_K [M_ * D_];
__device__ __align__(16) __half g_V [M_ * D_];
__device__ __align__(16) float  g_G [M_ * D_];
__device__ __align__(16) __half g_O [M_ * D_];

// ================= helpers =================
__device__ __forceinline__ uint32_t smem_u32(const void* p) {
    uint32_t a;
    asm("{ .reg .u64 t; cvta.to.shared.u64 t, %1; cvt.u32.u64 %0, t; }" : "=r"(a) : "l"(p));
    return a;
}
#define LDM_X4(r, addr) \
    asm volatile("ldmatrix.sync.aligned.m8n8.x4.shared.b16 {%0,%1,%2,%3}, [%4];" \
        : "=r"((r)[0]), "=r"((r)[1]), "=r"((r)[2]), "=r"((r)[3]) : "r"(addr))
#define LDM_X2(r, addr) \
    asm volatile("ldmatrix.sync.aligned.m8n8.x2.shared.b16 {%0,%1}, [%2];" \
        : "=r"((r)[0]), "=r"((r)[1]) : "r"(addr))
#define LDM_X2_T(r, addr) \
    asm volatile("ldmatrix.sync.aligned.m8n8.x2.trans.shared.b16 {%0,%1}, [%2];" \
        : "=r"((r)[0]), "=r"((r)[1]) : "r"(addr))
#define MMA_F16(c, a, b) \
    asm volatile("mma.sync.aligned.m16n8k16.row.col.f32.f16.f16.f32 " \
        "{%0,%1,%2,%3}, {%4,%5,%6,%7}, {%8,%9}, {%0,%1,%2,%3};" \
        : "+f"((c)[0]), "+f"((c)[1]), "+f"((c)[2]), "+f"((c)[3]) \
        : "r"((a)[0]), "r"((a)[1]), "r"((a)[2]), "r"((a)[3]), "r"((b)[0]), "r"((b)[1]))
#define CP_ASYNC16(dst, src) \
    asm volatile("cp.async.cg.shared.global [%0], [%1], 16;" :: "r"(dst), "l"(src))
#define CP_COMMIT() asm volatile("cp.async.commit_group;" ::: "memory")
#define CP_WAIT(n)  asm volatile("cp.async.wait_group %0;" :: "n"(n) : "memory")

__device__ __forceinline__ void split2h(float a, float b, uint32_t& h, uint32_t& l) {
    __half2 hi2 = __floats2half2_rn(a, b);
    float ra = a - __low2float(hi2);
    float rb = b - __high2float(hi2);
    __half2 lo2 = __floats2half2_rn(ra, rb);
    h = *reinterpret_cast<uint32_t*>(&hi2);
    l = *reinterpret_cast<uint32_t*>(&lo2);
}

// ================= fused prep kernel =================
__global__ void prep_all(const float* __restrict__ Qin, const float* __restrict__ Kin,
                         const float* __restrict__ Vin, const float* __restrict__ QT,
                         const float* __restrict__ KT,  const float* __restrict__ VT,
                         const float* __restrict__ GW,  const float* __restrict__ OW) {
    int blk = blockIdx.x;
    if (blk < 3072) {
        int z = blk >> 10;
        int bx = blk & 1023;
        const float* src = (z == 0) ? Qin : (z == 1) ? Kin : Vin;
        size_t base = (size_t)z * (M_ * D_);
        int i = bx * 256 + threadIdx.x;
        float4 v = reinterpret_cast<const float4*>(src)[i];
        __half2 a = __floats2half2_rn(v.x, v.y);
        __half2 b = __floats2half2_rn(v.z, v.w);
        reinterpret_cast<uint2*>(g_X + base)[i] =
            make_uint2(*reinterpret_cast<uint32_t*>(&a), *reinterpret_cast<uint32_t*>(&b));
    } else if (blk < 3200) {
        int t = blk - 3072;
        int z = t >> 6;
        int bx = t & 63;
        const float* src = (z == 0) ? GW : OW;
        size_t base = (size_t)(3 + z) * 65536;
        int i = bx * 256 + threadIdx.x;
        float4 v = reinterpret_cast<const float4*>(src)[i];
        uint32_t h0, l0, h1, l1;
        split2h(v.x, v.y, h0, l0);
        split2h(v.z, v.w, h1, l1);
        reinterpret_cast<uint2*>(g_Wh + base)[i] = make_uint2(h0, h1);
        reinterpret_cast<uint2*>(g_Wl + base)[i] = make_uint2(l0, l1);
    } else {
        int t = blk - 3200;
        int z = t >> 6;
        int ky = (t >> 3) & 7;
        int nx = t & 7;
        const float* src = (z == 0) ? QT : (z == 1) ? KT : VT;
        size_t base = (size_t)z * 65536;
        __shared__ float tr[32][33];
        int tx = threadIdx.x & 31, ty = threadIdx.x >> 5;
        int k0 = ky * 32, n0 = nx * 32;
#pragma unroll
        for (int r = 0; r < 4; r++)
            tr[ty + r * 8][tx] = src[(size_t)(k0 + ty + r * 8) * 256 + n0 + tx];
        __syncthreads();
#pragma unroll
        for (int r = 0; r < 4; r++) {
            int n = n0 + ty + r * 8, k = k0 + tx;
            float v = tr[tx][ty + r * 8];
            __half h = __float2half(v);
            g_Wh[base + (size_t)n * 256 + k] = h;
            g_Wl[base + (size_t)n * 256 + k] = __float2half(v - __half2float(h));
        }
    }
}

// ================= proj GEMM: BM=128, BN=64, BK=64, 3-stage =================
#define P_ROW   144
#define P_STAGE (256 * P_ROW)            // 36864
#define SMEM_PROJ (3 * P_STAGE)          // 110592

// MODE: 0 = split half out, 1 = f32+bias+sigmoid, 3 = single half out
template <int MODE>
__device__ __forceinline__ void proj_core(const __half* __restrict__ A,
                                          const __half* __restrict__ Bh, const __half* __restrict__ Bl,
                                          const float* __restrict__ bias,
                                          float* __restrict__ Yf,
                                          __half* __restrict__ Yh, __half* __restrict__ Yl) {
    extern __shared__ char smem[];
    const uint32_t sb = smem_u32(smem);
    const int tid = threadIdx.x, wid = tid >> 5, lane = tid & 31;
    const int warp_m = wid & 3, warp_n = wid >> 2;     // 4 x 2, warp tile 32x32
    const int m0 = blockIdx.y * 128, n0 = blockIdx.x * 64;
    const int lm_row = lane & 15, lm_chunk = (lane >> 4) * 16;

    float acc[2][4][4];
#pragma unroll
    for (int i = 0; i < 2; i++)
#pragma unroll
        for (int j = 0; j < 4; j++)
#pragma unroll
            for (int q = 0; q < 4; q++) acc[i][j][q] = 0.f;

    // stage BK=64 chunk: rows 0-127 A, 128-191 Bh, 192-255 Bl; 128B/row
    auto stage = [&](int kc, int buf) {
#pragma unroll
        for (int task = tid; task < 2048; task += 256) {
            int row = task >> 3, ch = task & 7;
            const __half* s;
            if (row < 128)      s = A  + (size_t)(m0 + row) * 256 + kc * 64 + ch * 8;
            else if (row < 192) s = Bh + (size_t)(n0 + row - 128) * 256 + kc * 64 + ch * 8;
            else                s = Bl + (size_t)(n0 + row - 192) * 256 + kc * 64 + ch * 8;
            CP_ASYNC16(sb + buf * P_STAGE + row * P_ROW + ch * 16, s);
        }
    };

    stage(0, 0); CP_COMMIT();
    stage(1, 1); CP_COMMIT();

    for (int kc = 0; kc < 4; kc++) {
        if (kc < 3) CP_WAIT(1); else CP_WAIT(0);
        __syncthreads();

        const uint32_t bb = sb + (kc % 3) * P_STAGE;
#pragma unroll
        for (int ks = 0; ks < 4; ks++) {
            const uint32_t kbyte = ks * 32 + lm_chunk;
            uint32_t a[2][4], bh[4][2], bl[4][2];
#pragma unroll
            for (int mf = 0; mf < 2; mf++) {
                uint32_t off = (uint32_t)((warp_m * 32 + mf * 16 + lm_row) * P_ROW) + kbyte;
                LDM_X4(a[mf], bb + off);
            }
#pragma unroll
            for (int np = 0; np < 2; np++) {
                uint32_t off = (uint32_t)((128 + warp_n * 32 + np * 16 + lm_row) * P_ROW) + kbyte;
                uint32_t th[4], tl[4];
                LDM_X4(th, bb + off);
                LDM_X4(tl, bb + 64 * P_ROW + off);
                bh[np * 2][0] = th[0]; bh[np * 2][1] = th[2];
                bh[np * 2 + 1][0] = th[1]; bh[np * 2 + 1][1] = th[3];
                bl[np * 2][0] = tl[0]; bl[np * 2][1] = tl[2];
                bl[np * 2 + 1][0] = tl[1]; bl[np * 2 + 1][1] = tl[3];
            }
#pragma unroll
            for (int mf = 0; mf < 2; mf++)
#pragma unroll
                for (int nf = 0; nf < 4; nf++) {
                    MMA_F16(acc[mf][nf], a[mf], bh[nf]);
                    MMA_F16(acc[mf][nf], a[mf], bl[nf]);
                }
        }

        if (kc + 2 < 4) { stage(kc + 2, (kc + 2) % 3); CP_COMMIT(); }
    }

    // epilogue
#pragma unroll
    for (int mf = 0; mf < 2; mf++) {
        int row = m0 + warp_m * 32 + mf * 16 + (lane >> 2);
#pragma unroll
        for (int nf = 0; nf < 4; nf++) {
            int col = n0 + warp_n * 32 + nf * 8 + (lane & 3) * 2;
            float v0 = acc[mf][nf][0], v1 = acc[mf][nf][1];
            float v2 = acc[mf][nf][2], v3 = acc[mf][nf][3];
            if (MODE == 1) {
                float b0 = bias[col], b1 = bias[col + 1];
                v0 += b0; v1 += b1; v2 += b0; v3 += b1;
                v0 = 1.f / (1.f + __expf(-v0));
                v1 = 1.f / (1.f + __expf(-v1));
                v2 = 1.f / (1.f + __expf(-v2));
                v3 = 1.f / (1.f + __expf(-v3));
                *reinterpret_cast<float2*>(Yf + (size_t)row * 256 + col)       = make_float2(v0, v1);
                *reinterpret_cast<float2*>(Yf + (size_t)(row + 8) * 256 + col) = make_float2(v2, v3);
            } else if (MODE == 0) {
                uint32_t h0, l0, h1, l1;
                split2h(v0, v1, h0, l0);
                split2h(v2, v3, h1, l1);
                *reinterpret_cast<uint32_t*>(Yh + (size_t)row * 256 + col)       = h0;
                *reinterpret_cast<uint32_t*>(Yl + (size_t)row * 256 + col)       = l0;
                *reinterpret_cast<uint32_t*>(Yh + (size_t)(row + 8) * 256 + col) = h1;
                *reinterpret_cast<uint32_t*>(Yl + (size_t)(row + 8) * 256 + col) = l1;
            } else {
                __half2 a2 = __floats2half2_rn(v0, v1);
                __half2 b2 = __floats2half2_rn(v2, v3);
                *reinterpret_cast<uint32_t*>(Yh + (size_t)row * 256 + col)       = *reinterpret_cast<uint32_t*>(&a2);
                *reinterpret_cast<uint32_t*>(Yh + (size_t)(row + 8) * 256 + col) = *reinterpret_cast<uint32_t*>(&b2);
            }
        }
    }
}

__global__ void __launch_bounds__(256, 2)
proj_kernel(const float* __restrict__ Gb) {
    int z = blockIdx.z;
    int xslot = (z == 3) ? 2 : z;
    const __half* A  = g_X + (size_t)xslot * (M_ * D_);
    const __half* Bh = g_Wh + (size_t)z * 65536;
    const __half* Bl = g_Wl + (size_t)z * 65536;
    if (z == 0)      proj_core<0>(A, Bh, Bl, nullptr, nullptr, g_Qh, g_Ql);
    else if (z == 1) proj_core<3>(A, Bh, Bl, nullptr, nullptr, g_K, nullptr);
    else if (z == 2) proj_core<3>(A, Bh, Bl, nullptr, nullptr, g_V, nullptr);
    else             proj_core<1>(A, Bh, Bl, Gb, g_G, nullptr, nullptr);
}

// ================= out GEMM: BM=64, BN=64, BK=128 (R9, unchanged) =================
#define G_ROW  272
#define GBM    64
#define GBN    64
#define STAGE_ ((GBM + 2 * GBN) * G_ROW)
#define SMEM_OUT (2 * STAGE_)

__global__ void __launch_bounds__(256, 2)
out_kernel(const float* __restrict__ Ob, float* __restrict__ out) {
    extern __shared__ char smem[];
    const uint32_t sb = smem_u32(smem);
    const __half* A  = g_O;
    const __half* Bh = g_Wh + 4 * 65536;
    const __half* Bl = g_Wl + 4 * 65536;
    const int tid = threadIdx.x, wid = tid >> 5, lane = tid & 31;
    const int warp_m = wid & 1, warp_n = wid >> 1;
    const int m0 = blockIdx.y * GBM, n0 = blockIdx.x * GBN;
    const int lm_row = lane & 15, lm_chunk = (lane >> 4) * 16;

    float acc[2][2][4];
#pragma unroll
    for (int i = 0; i < 2; i++)
#pragma unroll
        for (int j = 0; j < 2; j++)
#pragma unroll
            for (int q = 0; q < 4; q++) acc[i][j][q] = 0.f;

    auto stage = [&](int kc, int buf) {
#pragma unroll
        for (int task = tid; task < 3072; task += 256) {
            int row = task >> 4;
            int ch  = task & 15;
            const __half* s;
            uint32_t dbase;
            if (row < GBM) {
                s = A + (size_t)(m0 + row) * 256 + kc * 128 + ch * 8;
                dbase = (uint32_t)(row * G_ROW);
            } else if (row < GBM + GBN) {
                int r = row - GBM;
                s = Bh + (size_t)(n0 + r) * 256 + kc * 128 + ch * 8;
                dbase = (uint32_t)((GBM + r) * G_ROW);
            } else {
                int r = row - GBM - GBN;
                s = Bl + (size_t)(n0 + r) * 256 + kc * 128 + ch * 8;
                dbase = (uint32_t)((GBM + GBN + r) * G_ROW);
            }
            CP_ASYNC16(sb + buf * STAGE_ + dbase + ch * 16, s);
        }
    };

    stage(0, 0); CP_COMMIT();
    stage(1, 1); CP_COMMIT();

#pragma unroll
    for (int kc = 0; kc < 2; kc++) {
        if (kc == 0) CP_WAIT(1); else CP_WAIT(0);
        __syncthreads();

        const uint32_t bb = sb + kc * STAGE_;
#pragma unroll
        for (int ks = 0; ks < 8; ks++) {
            const uint32_t kbyte = ks * 32 + lm_chunk;
            uint32_t a[2][4], bh[2][2], bl[2][2];
#pragma unroll
            for (int mf = 0; mf < 2; mf++) {
                uint32_t off = (uint32_t)((warp_m * 32 + mf * 16 + lm_row) * G_ROW) + kbyte;
                LDM_X4(a[mf], bb + off);
            }
            {
                uint32_t off = (uint32_t)((warp_n * 16 + lm_row) * G_ROW) + kbyte;
                uint32_t th[4], tl[4];
                LDM_X4(th, bb + GBM * G_ROW + off);
                LDM_X4(tl, bb + (GBM + GBN) * G_ROW + off);
                bh[0][0] = th[0]; bh[0][1] = th[2];
                bh[1][0] = th[1]; bh[1][1] = th[3];
                bl[0][0] = tl[0]; bl[0][1] = tl[2];
                bl[1][0] = tl[1]; bl[1][1] = tl[3];
            }
#pragma unroll
            for (int mf = 0; mf < 2; mf++)
#pragma unroll
                for (int nf = 0; nf < 2; nf++) {
                    MMA_F16(acc[mf][nf], a[mf], bh[nf]);
                    MMA_F16(acc[mf][nf], a[mf], bl[nf]);
                }
        }
    }

#pragma unroll
    for (int mf = 0; mf < 2; mf++) {
        int row = m0 + warp_m * 32 + mf * 16 + (lane >> 2);
#pragma unroll
        for (int nf = 0; nf < 2; nf++) {
            int col = n0 + warp_n * 16 + nf * 8 + (lane & 3) * 2;
            float b0 = Ob[col], b1 = Ob[col + 1];
            float v0 = acc[mf][nf][0] + b0, v1 = acc[mf][nf][1] + b1;
            float v2 = acc[mf][nf][2] + b0, v3 = acc[mf][nf][3] + b1;
            *reinterpret_cast<float2*>(out + (size_t)row * 256 + col)       = make_float2(v0, v1);
            *reinterpret_cast<float2*>(out + (size_t)(row + 8) * 256 + col) = make_float2(v2, v3);
        }
    }
}

// ================= fp16 tensor-core local-window attention (R9) =================
#define A_QH 0
#define A_QL 2560
#define A_K  5120
#define A_V  12800
#define A_PH 20480
#define A_PL 27136
#define A_RED 33792
#define A_TOTAL 34816
#define QK_ROW 80
#define VT_ROW 208

__global__ void __launch_bounds__(256)
attn_kernel() {
    __shared__ __align__(16) char sm[A_TOTAL];
    const uint32_t sb = smem_u32(sm);
    float* red = reinterpret_cast<float*>(sm + A_RED);

    const int b = blockIdx.z, h = blockIdx.y, s0 = blockIdx.x * 32;
    const int tid = threadIdx.x, wid = tid >> 5, lane = tid & 31;
    const int lm_row = lane & 15, lm_chunk = (lane >> 4) * 16;

    for (int i = tid; i < 384; i += 256) {
        int row = i >> 2, ch = i & 3;
        int t = s0 - 32 + row;
        uint4 vk = make_uint4(0, 0, 0, 0), vv = vk;
        if (t >= 0 && t < S_) {
            size_t e = (size_t)(b * S_ + t) * 256 + h * 32 + ch * 8;
            vk = *reinterpret_cast<const uint4*>(g_K + e);
            vv = *reinterpret_cast<const uint4*>(g_V + e);
        }
        *reinterpret_cast<uint4*>(sm + A_K + row * QK_ROW + ch * 16) = vk;
        *reinterpret_cast<uint4*>(sm + A_V + row * QK_ROW + ch * 16) = vv;
    }
    for (int i = tid; i < 128; i += 256) {
        int row = i >> 2, ch = i & 3;
        size_t e = (size_t)(b * S_ + s0 + row) * 256 + h * 32 + ch * 8;
        *reinterpret_cast<uint4*>(sm + A_QH + row * QK_ROW + ch * 16) =
            *reinterpret_cast<const uint4*>(g_Qh + e);
        *reinterpret_cast<uint4*>(sm + A_QL + row * QK_ROW + ch * 16) =
            *reinterpret_cast<const uint4*>(g_Ql + e);
    }
    __syncthreads();

    const int mf = wid >> 2;
    const int nfb = (wid & 3) * 3;
    float sc[3][4];
#pragma unroll
    for (int j = 0; j < 3; j++)
#pragma unroll
        for (int q = 0; q < 4; q++) sc[j][q] = 0.f;

#pragma unroll
    for (int kf = 0; kf < 2; kf++) {
        uint32_t qh[4], ql[4];
        uint32_t aoff = (uint32_t)((mf * 16 + lm_row) * QK_ROW) + kf * 32 + lm_chunk;
        LDM_X4(qh, sb + A_QH + aoff);
        LDM_X4(ql, sb + A_QL + aoff);
#pragma unroll
        for (int j = 0; j < 3; j++) {
            uint32_t kk[2];
            uint32_t boff = (uint32_t)(((nfb + j) * 8 + (lane & 7)) * QK_ROW) + kf * 32 +
                            (((lane >> 3) & 1) * 16);
            LDM_X2(kk, sb + A_K + boff);
            MMA_F16(sc[j], qh, kk);
            MMA_F16(sc[j], ql, kk);
        }
    }

    const float rsC = 0.17677669529663689f;
    const int r0 = mf * 16 + (lane >> 2);
    const int r1 = r0 + 8;
    float sv[3][4];
#pragma unroll
    for (int j = 0; j < 3; j++) {
        int nb = (nfb + j) * 8 + (lane & 3) * 2;
#pragma unroll
        for (int q = 0; q < 4; q++) {
            int n = nb + (q & 1);
            int row = (q < 2) ? r0 : r1;
            int t = s0 - 32 + n;
            bool ok = (n >= row) && (n <= row + 64) && (t >= 0) && (t < S_);
            sv[j][q] = ok ? sc[j][q] * rsC : -1e30f;
        }
    }
    float m0 = -1e30f, m1 = -1e30f;
#pragma unroll
    for (int j = 0; j < 3; j++) {
        m0 = fmaxf(m0, fmaxf(sv[j][0], sv[j][1]));
        m1 = fmaxf(m1, fmaxf(sv[j][2], sv[j][3]));
    }
    m0 = fmaxf(m0, __shfl_xor_sync(0xffffffffu, m0, 1));
    m0 = fmaxf(m0, __shfl_xor_sync(0xffffffffu, m0, 2));
    m1 = fmaxf(m1, __shfl_xor_sync(0xffffffffu, m1, 1));
    m1 = fmaxf(m1, __shfl_xor_sync(0xffffffffu, m1, 2));
    if ((lane & 3) == 0) {
        red[r0 * 8 + (wid & 3)] = m0;
        red[r1 * 8 + (wid & 3)] = m1;
    }
    __syncthreads();
    float mx0 = fmaxf(fmaxf(red[r0 * 8 + 0], red[r0 * 8 + 1]),
                      fmaxf(red[r0 * 8 + 2], red[r0 * 8 + 3]));
    float mx1 = fmaxf(fmaxf(red[r1 * 8 + 0], red[r1 * 8 + 1]),
                      fmaxf(red[r1 * 8 + 2], red[r1 * 8 + 3]));
    float e[3][4], sum0 = 0.f, sum1 = 0.f;
#pragma unroll
    for (int j = 0; j < 3; j++) {
        e[j][0] = __expf(sv[j][0] - mx0);
        e[j][1] = __expf(sv[j][1] - mx0);
        e[j][2] = __expf(sv[j][2] - mx1);
        e[j][3] = __expf(sv[j][3] - mx1);
        sum0 += e[j][0] + e[j][1];
        sum1 += e[j][2] + e[j][3];
    }
    sum0 += __shfl_xor_sync(0xffffffffu, sum0, 1);
    sum0 += __shfl_xor_sync(0xffffffffu, sum0, 2);
    sum1 += __shfl_xor_sync(0xffffffffu, sum1, 1);
    sum1 += __shfl_xor_sync(0xffffffffu, sum1, 2);
    if ((lane & 3) == 0) {
        red[r0 * 8 + 4 + (wid & 3)] = sum0;
        red[r1 * 8 + 4 + (wid & 3)] = sum1;
    }
    __syncthreads();
    float inv0 = 1.f / (red[r0 * 8 + 4] + red[r0 * 8 + 5] + red[r0 * 8 + 6] + red[r0 * 8 + 7]);
    float inv1 = 1.f / (red[r1 * 8 + 4] + red[r1 * 8 + 5] + red[r1 * 8 + 6] + red[r1 * 8 + 7]);

#pragma unroll
    for (int j = 0; j < 3; j++) {
        int nb = (nfb + j) * 8 + (lane & 3) * 2;
        uint32_t h0, l0, h1, l1;
        split2h(e[j][0] * inv0, e[j][1] * inv0, h0, l0);
        split2h(e[j][2] * inv1, e[j][3] * inv1, h1, l1);
        *reinterpret_cast<uint32_t*>(sm + A_PH + r0 * VT_ROW + nb * 2) = h0;
        *reinterpret_cast<uint32_t*>(sm + A_PL + r0 * VT_ROW + nb * 2) = l0;
        *reinterpret_cast<uint32_t*>(sm + A_PH + r1 * VT_ROW + nb * 2) = h1;
        *reinterpret_cast<uint32_t*>(sm + A_PL + r1 * VT_ROW + nb * 2) = l1;
    }
    __syncthreads();

    const int nc = wid & 3;
    float oaccH[4] = {0.f, 0.f, 0.f, 0.f};
    float oaccL[4] = {0.f, 0.f, 0.f, 0.f};
#pragma unroll
    for (int kf = 0; kf < 6; kf++) {
        uint32_t ph[4], pl[4], vv[2];
        uint32_t poff = (uint32_t)((mf * 16 + lm_row) * VT_ROW) + kf * 32 + lm_chunk;
        LDM_X4(ph, sb + A_PH + poff);
        LDM_X4(pl, sb + A_PL + poff);
        uint32_t voff = (uint32_t)((kf * 16 + (lane & 15)) * QK_ROW) + nc * 16;
        LDM_X2_T(vv, sb + A_V + voff);
        MMA_F16(oaccH, ph, vv);
        MMA_F16(oaccL, pl, vv);
    }

    {
        int gcol = h * 32 + nc * 8 + (lane & 3) * 2;
        size_t e0 = (size_t)(b * S_ + s0 + r0) * 256 + gcol;
        size_t e1 = (size_t)(b * S_ + s0 + r1) * 256 + gcol;
        float2 gA = *reinterpret_cast<const float2*>(g_G + e0);
        float2 gB = *reinterpret_cast<const float2*>(g_G + e1);
        __half2 o0 = __floats2half2_rn((oaccH[0] + oaccL[0]) * gA.x, (oaccH[1] + oaccL[1]) * gA.y);
        __half2 o1 = __floats2half2_rn((oaccH[2] + oaccL[2]) * gB.x, (oaccH[3] + oaccL[3]) * gB.y);
        *reinterpret_cast<uint32_t*>(g_O + e0) = *reinterpret_cast<uint32_t*>(&o0);
        *reinterpret_cast<uint32_t*>(g_O + e1) = *reinterpret_cast<uint32_t*>(&o1);
    }
}

// ============================================================
extern "C" void kernel_launch(void* const* d_in, const int* in_sizes, int n_in,
                              void* d_out, int out_size) {
    const float* Qin = (const float*)d_in[0];
    const float* Kin = (const float*)d_in[1];
    const float* Vin = (const float*)d_in[2];
    const float* QT  = (const float*)d_in[3];
    const float* KT  = (const float*)d_in[4];
    const float* VT  = (const float*)d_in[5];
    const float* GW  = (const float*)d_in[6];
    const float* Gb  = (const float*)d_in[7];
    const float* OW  = (const float*)d_in[8];
    const float* Ob  = (const float*)d_in[9];
    float* out = (float*)d_out;

    cudaFuncSetAttribute(proj_kernel, cudaFuncAttributeMaxDynamicSharedMemorySize, SMEM_PROJ);
    cudaFuncSetAttribute(out_kernel,  cudaFuncAttributeMaxDynamicSharedMemorySize, SMEM_OUT);

    prep_all<<<3392, 256>>>(Qin, Kin, Vin, QT, KT, VT, GW, OW);
    proj_kernel<<<dim3(4, 32, 4), 256, SMEM_PROJ>>>(Gb);
    attn_kernel<<<dim3(S_ / 32, H_, B_), 256>>>();
    out_kernel<<<dim3(4, 64, 1), 256, SMEM_OUT>>>(Ob, out);
}